// round 5
// baseline (speedup 1.0000x reference)
#include <cuda_runtime.h>
#include <cstdint>
#include <math.h>

#define NMAXA 8192
#define PMAXP 131072

typedef unsigned long long ull;

// ---------------- device scratch ----------------
__device__ float g_cgw[4096];                      // dense CG [aF][bF*16+MF]
__device__ float g_sym0[136 * 16];
__device__ float g_sym1[45 * 16];
__device__ float g_sym2[10 * 4];
__device__ float g_c000[1];
__device__ float g_emb[NMAXA * 32];
__device__ float g_feats[(size_t)NMAXA * 1920];
__device__ float g_featsB[(size_t)NMAXA * 1920];
__device__ float g_S[NMAXA * 240];
__device__ float g_W[(size_t)PMAXP * 256];         // per-pair W (sorted order)
__device__ float g_Et[16 * PMAXP];                 // transposed edge vectors (sorted order)
__device__ int   g_snbr[PMAXP];
__device__ int   g_counts[NMAXA];
__device__ int   g_starts[NMAXA];
__device__ int   g_cursor[NMAXA];
__device__ int   g_sorted[PMAXP];

struct CGBuf { float v[3436]; };

__device__ __forceinline__ int shoff(int l) { return l==0?0:l==1?1:l==2?4:9; }

__device__ constexpr int OFFS[16] = {0,256,448,640,832,960,1088,1216,1344,
                                     1472,1536,1600,1664,1728,1792,1856};

__constant__ int c_e_l1[34]={0,0,0,0, 1,1,1,1,1,1,1,1,1, 2,2,2,2,2,2,2,2,2,2,2, 3,3,3,3,3,3,3,3,3,3};
__constant__ int c_e_l2[34]={0,1,2,3, 0,1,1,1,2,2,2,3,3, 0,1,1,1,2,2,2,2,3,3,3, 0,1,1,2,2,2,3,3,3,3};
__constant__ int c_e_L [34]={0,1,2,3, 1,0,1,2,1,2,3,2,3, 2,1,2,3,0,1,2,3,1,2,3, 3,2,3,1,2,3,0,1,2,3};
__constant__ int c_e_off[34]={0,1,10,35, 84,93,102,129,174,219,294,399,504,
                              651,676,721,796,901,926,1001,1126,1301,1406,1581,
                              1826,1875,1980,2127,2232,2407,2652,2701,2848,3093};

#define FMA2(ACC,PD,CV) asm("fma.rn.f32x2 %0, %1, %2, %0;" : "+l"(ACC) : "l"(PD), "l"(CV))
#define MUL2(OUT,A,B)   asm("mul.rn.f32x2 %0, %1, %2;" : "=l"(OUT) : "l"(A), "l"(B))
#define PACK2(PD,P)     asm("mov.b64 %0, {%1, %1};" : "=l"(PD) : "f"(P))
#define UNPK2(LO,HI,PD) asm("mov.b64 {%0, %1}, %2;" : "=f"(LO), "=f"(HI) : "l"(PD))

// ---------------- CG build ----------------
__global__ void k_initcg(CGBuf cg) {
    int t = threadIdx.x;
    for (int i = t; i < 4096; i += 256) g_cgw[i] = 0.f;
    __syncthreads();
    for (int e = 0; e < 34; e++) {
        int l1 = c_e_l1[e], l2 = c_e_l2[e], L = c_e_L[e];
        int d2 = 2*l2+1, dL = 2*L+1;
        int sz = (2*l1+1)*d2*dL, off = c_e_off[e];
        for (int i = t; i < sz; i += 256) {
            int M = i % dL; int r = i / dL; int b = r % d2; int a = r / d2;
            g_cgw[(shoff(l1)+a)*256 + (shoff(l2)+b)*16 + shoff(L)+M] = cg.v[off + i];
        }
        __syncthreads();
    }
    for (int i = t; i < 136*16; i += 256) {
        int pi = i >> 4, M = i & 15;
        int a = 0, base = 0;
        while (base + (16 - a) <= pi) { base += 16 - a; a++; }
        int b = a + (pi - base);
        float v = g_cgw[a*256 + b*16 + M];
        if (a != b) v += g_cgw[b*256 + a*16 + M];
        g_sym0[i] = v;
    }
    for (int i = t; i < 45*16; i += 256) {
        int pi = i >> 4, M = i & 15;
        int a = 0, base = 0;
        while (base + (9 - a) <= pi) { base += 9 - a; a++; }
        int b = a + (pi - base);
        float v = 0.f;
        if (M < 9) {
            v = g_cgw[a*256 + b*16 + M];
            if (a != b) v += g_cgw[b*256 + a*16 + M];
        }
        g_sym1[i] = v;
    }
    for (int i = t; i < 40; i += 256) {
        int pi = i >> 2, M = i & 3;
        int a = 0, base = 0;
        while (base + (4 - a) <= pi) { base += 4 - a; a++; }
        int b = a + (pi - base);
        float v = g_cgw[a*256 + b*16 + M];
        if (a != b) v += g_cgw[b*256 + a*16 + M];
        g_sym2[i] = v;
    }
    if (t == 0) g_c000[0] = g_cgw[0];
}

// ---------------- init: embeddings + zero ----------------
__global__ void k_misc1(const float* __restrict__ tab, const int* __restrict__ spec, int N) {
    int i = blockIdx.x * blockDim.x + threadIdx.x;
    if (i < N * 32) g_emb[i] = tab[spec[i >> 5] * 32 + (i & 31)];
    if (i < N) g_counts[i] = 0;
    if (i < N * 240) g_S[i] = 0.f;
}

__global__ void k_hist(const int* __restrict__ centers, int P) {
    int p = blockIdx.x * blockDim.x + threadIdx.x;
    if (p < P) atomicAdd(&g_counts[centers[p]], 1);
}

__global__ void k_scan(int N) {
    __shared__ int sh[1024];
    __shared__ int sCarry;
    int t = threadIdx.x;
    if (t == 0) sCarry = 0;
    __syncthreads();
    for (int base = 0; base < N; base += 1024) {
        int i = base + t;
        int v = (i < N) ? g_counts[i] : 0;
        sh[t] = v; __syncthreads();
        for (int off = 1; off < 1024; off <<= 1) {
            int tv = (t >= off) ? sh[t - off] : 0;
            __syncthreads();
            sh[t] += tv;
            __syncthreads();
        }
        int ex = sCarry + sh[t] - v;
        if (i < N) { g_starts[i] = ex; g_cursor[i] = ex; }
        __syncthreads();
        if (t == 0) sCarry += sh[1023];
        __syncthreads();
    }
}

__global__ void k_scatter(const int* __restrict__ centers, int P) {
    int p = blockIdx.x * blockDim.x + threadIdx.x;
    if (p < P) { int pos = atomicAdd(&g_cursor[centers[p]], 1); g_sorted[pos] = p; }
}

// ---------------- edge vectors (transposed, sorted order) ----------------
__global__ void k_edge(const float* __restrict__ sh, const float* __restrict__ rb,
                       const int* __restrict__ neighbors, int P) {
    int idx = blockIdx.x * blockDim.x + threadIdx.x;
    if (idx >= 16 * P) return;
    int a = idx / P, pos = idx % P;
    int p = g_sorted[pos];
    if (a == 0) g_snbr[pos] = neighbors[p];
    int l   = (a==0)?0:(a<4)?1:(a<9)?2:3;
    int nrl = (l==0?8:l==1?6:l==2?4:2);
    int rbo = (l==0?0:l==1?8:l==2?14:18);
    float s = 0.f;
    for (int r = 0; r < nrl; r++) s += rb[p*20 + rbo + r];
    g_Et[a * PMAXP + pos] = sh[p*16 + a] * 0.1f * s;
}

// ---------------- W = E @ CG  (64 pairs per block) ----------------
__global__ void __launch_bounds__(256) k_W2(int P) {
    __shared__ float sEt[16 * 64];
    int t = threadIdx.x;
    int p0 = blockIdx.x * 64;
    for (int j = t; j < 1024; j += 256) {
        int a = j >> 6, i = j & 63;
        sEt[j] = (p0 + i < P) ? g_Et[a * PMAXP + p0 + i] : 0.f;
    }
    ull cAd[16];
    #pragma unroll
    for (int a = 0; a < 16; a++) { float c = g_cgw[a*256 + t]; PACK2(cAd[a], c); }
    __syncthreads();
    for (int i = 0; i < 64; i += 4) {
        ull acc01 = 0ull, acc23 = 0ull;
        #pragma unroll
        for (int a = 0; a < 16; a++) {
            ulonglong2 e2 = *(const ulonglong2*)(sEt + a*64 + i);
            FMA2(acc01, e2.x, cAd[a]);
            FMA2(acc23, e2.y, cAd[a]);
        }
        float v0, v1, v2, v3;
        UNPK2(v0, v1, acc01); UNPK2(v2, v3, acc23);
        if (p0 + i + 3 < P) {
            g_W[(size_t)(p0+i  )*256 + t] = v0;
            g_W[(size_t)(p0+i+1)*256 + t] = v1;
            g_W[(size_t)(p0+i+2)*256 + t] = v2;
            g_W[(size_t)(p0+i+3)*256 + t] = v3;
        } else {
            if (p0+i   < P) g_W[(size_t)(p0+i  )*256 + t] = v0;
            if (p0+i+1 < P) g_W[(size_t)(p0+i+1)*256 + t] = v1;
            if (p0+i+2 < P) g_W[(size_t)(p0+i+2)*256 + t] = v2;
            if (p0+i+3 < P) g_W[(size_t)(p0+i+3)*256 + t] = v3;
        }
    }
}

// ---------------- invariant MP ----------------
__global__ void k_invA(const float* __restrict__ sh, const float* __restrict__ rb,
                       const int* __restrict__ centers, const int* __restrict__ neighbors,
                       const int* __restrict__ spec, int P) {
    int idx = blockIdx.x * blockDim.x + threadIdx.x;
    int p = idx >> 6, j = idx & 63;
    if (p >= P || j >= 60) return;
    int l, m, nr;
    if (j < 8)       { l = 0; m = 0;        nr = j; }
    else if (j < 26) { l = 1; int r = j-8;  m = r/6; nr = r%6; }
    else if (j < 46) { l = 2; int r = j-26; m = r/4; nr = r%4; }
    else             { l = 3; int r = j-46; m = r/2; nr = r%2; }
    int shf = shoff(l) + m;
    int rbf = (l==0?0:l==1?8:l==2?14:18) + nr;
    float val = sh[p*16 + shf] * 0.1f * rb[p*20 + rbf];
    int s = spec[neighbors[p]];
    atomicAdd(&g_S[(centers[p]*4 + s)*60 + j], val);
}

__global__ void k_invB(const float* __restrict__ tab, int N) {
    int idx = blockIdx.x * blockDim.x + threadIdx.x;
    if (idx >= N * 1920) return;
    int n = idx / 1920, f = idx % 1920;
    int l, m, k;
    if (f < 256)       { l = 0; m = 0;         k = f; }
    else if (f < 832)  { l = 1; int r = f-256; m = r/192; k = r%192; }
    else if (f < 1472) { l = 2; int r = f-832; m = r/128; k = r%128; }
    else               { l = 3; int r = f-1472;m = r/64;  k = r%64; }
    int nr = k >> 5, c = k & 31;
    int nrl = (l==0?8:l==1?6:l==2?4:2);
    int jb  = (l==0?0:l==1?8:l==2?26:46);
    int j = jb + m*nrl + nr;
    const float* Sp = &g_S[n*240 + j];
    float s = 0.f;
    #pragma unroll
    for (int sp = 0; sp < 4; sp++) s += Sp[sp*60] * tab[sp*32 + c];
    g_feats[(size_t)n*1920 + f] = 0.1f * s;
}

// ---------------- tensor product, per k-class ----------------
__global__ void __launch_bounds__(256) k_tp0(float* __restrict__ F, int N) {
    __shared__ float sC[136 * 16];
    int t = threadIdx.x;
    for (int i = t; i < 2176; i += 256) sC[i] = g_sym0[i];
    __syncthreads();
    int atom = blockIdx.x * 4 + (t >> 6);
    if (atom >= N) return;
    float* row = F + (size_t)atom * 1920 + (t & 63);
    float A[16];
    A[0]=row[0];    A[1]=row[256];  A[2]=row[448];  A[3]=row[640];
    A[4]=row[832];  A[5]=row[960];  A[6]=row[1088]; A[7]=row[1216]; A[8]=row[1344];
    A[9]=row[1472]; A[10]=row[1536];A[11]=row[1600];A[12]=row[1664];
    A[13]=row[1728];A[14]=row[1792];A[15]=row[1856];
    ull acc[8];
    #pragma unroll
    for (int i = 0; i < 8; i++) acc[i] = 0ull;
    #pragma unroll
    for (int a = 0; a < 16; a++) {
        #pragma unroll
        for (int b = a; b < 16; b++) {
            const int pi = a*16 - a*(a-1)/2 + (b - a);
            float P = A[a] * A[b];
            ull Pd; PACK2(Pd, P);
            const ulonglong2* c2 = (const ulonglong2*)(sC + pi*16);
            ulonglong2 cv0 = c2[0];
            ulonglong2 cv1 = c2[1];
            FMA2(acc[0], Pd, cv0.x); FMA2(acc[1], Pd, cv0.y);
            FMA2(acc[2], Pd, cv1.x); FMA2(acc[3], Pd, cv1.y);
            ulonglong2 cv2 = c2[2];
            ulonglong2 cv3 = c2[3];
            FMA2(acc[4], Pd, cv2.x); FMA2(acc[5], Pd, cv2.y);
            FMA2(acc[6], Pd, cv3.x); FMA2(acc[7], Pd, cv3.y);
        }
    }
    float v[16];
    #pragma unroll
    for (int i = 0; i < 8; i++) UNPK2(v[2*i], v[2*i+1], acc[i]);
    row[0]   =A[0] +0.1f*v[0];  row[256] =A[1] +0.1f*v[1];  row[448] =A[2] +0.1f*v[2];
    row[640] =A[3] +0.1f*v[3];  row[832] =A[4] +0.1f*v[4];  row[960] =A[5] +0.1f*v[5];
    row[1088]=A[6] +0.1f*v[6];  row[1216]=A[7] +0.1f*v[7];  row[1344]=A[8] +0.1f*v[8];
    row[1472]=A[9] +0.1f*v[9];  row[1536]=A[10]+0.1f*v[10]; row[1600]=A[11]+0.1f*v[11];
    row[1664]=A[12]+0.1f*v[12]; row[1728]=A[13]+0.1f*v[13]; row[1792]=A[14]+0.1f*v[14];
    row[1856]=A[15]+0.1f*v[15];
}

__global__ void __launch_bounds__(256) k_tp1(float* __restrict__ F, int N) {
    __shared__ float sC[45 * 16];
    int t = threadIdx.x;
    for (int i = t; i < 720; i += 256) sC[i] = g_sym1[i];
    __syncthreads();
    int atom = blockIdx.x * 4 + (t >> 6);
    if (atom >= N) return;
    float* row = F + (size_t)atom * 1920 + 64 + (t & 63);
    float A[9];
    A[0]=row[0];   A[1]=row[256]; A[2]=row[448]; A[3]=row[640];
    A[4]=row[832]; A[5]=row[960]; A[6]=row[1088];A[7]=row[1216];A[8]=row[1344];
    ull acc[4];
    #pragma unroll
    for (int i = 0; i < 4; i++) acc[i] = 0ull;
    float acc8 = 0.f;
    #pragma unroll
    for (int a = 0; a < 9; a++) {
        #pragma unroll
        for (int b = a; b < 9; b++) {
            const int pi = a*9 - a*(a-1)/2 + (b - a);
            float P = A[a] * A[b];
            ull Pd; PACK2(Pd, P);
            const ulonglong2* c2 = (const ulonglong2*)(sC + pi*16);
            ulonglong2 cv0 = c2[0];
            ulonglong2 cv1 = c2[1];
            FMA2(acc[0], Pd, cv0.x); FMA2(acc[1], Pd, cv0.y);
            FMA2(acc[2], Pd, cv1.x); FMA2(acc[3], Pd, cv1.y);
            acc8 += P * sC[pi*16 + 8];
        }
    }
    float v[8];
    #pragma unroll
    for (int i = 0; i < 4; i++) UNPK2(v[2*i], v[2*i+1], acc[i]);
    row[0]   =A[0]+0.1f*v[0]; row[256] =A[1]+0.1f*v[1]; row[448] =A[2]+0.1f*v[2];
    row[640] =A[3]+0.1f*v[3]; row[832] =A[4]+0.1f*v[4]; row[960] =A[5]+0.1f*v[5];
    row[1088]=A[6]+0.1f*v[6]; row[1216]=A[7]+0.1f*v[7]; row[1344]=A[8]+0.1f*acc8;
}

__global__ void k_tp23(float* __restrict__ F, int N) {
    int t = threadIdx.x;
    int atom = blockIdx.x * 2 + (t >> 7);
    if (atom >= N) return;
    int tt = t & 127;
    if (tt < 64) {
        float* row = F + (size_t)atom * 1920 + 128 + tt;
        float A[4];
        A[0]=row[0]; A[1]=row[256]; A[2]=row[448]; A[3]=row[640];
        float acc[4] = {0.f, 0.f, 0.f, 0.f};
        #pragma unroll
        for (int a = 0; a < 4; a++) {
            #pragma unroll
            for (int b = a; b < 4; b++) {
                const int pi = a*4 - a*(a-1)/2 + (b - a);
                float P = A[a] * A[b];
                #pragma unroll
                for (int M = 0; M < 4; M++) acc[M] += P * g_sym2[pi*4 + M];
            }
        }
        row[0]  =A[0]+0.1f*acc[0]; row[256]=A[1]+0.1f*acc[1];
        row[448]=A[2]+0.1f*acc[2]; row[640]=A[3]+0.1f*acc[3];
    } else {
        float* row = F + (size_t)atom * 1920 + 192 + (tt & 63);
        float A = row[0];
        row[0] = A + 0.1f * A * A * g_c000[0];
    }
}

// ---------------- equivariant MP v4: warp-per-center, EF read-once, emb fused ----------------
__device__ __forceinline__ void fma_kb0(ull* acc, ull v, const float* sW, int b) {
    #pragma unroll
    for (int mp = 0; mp < 8; mp++) {
        ulonglong2 w2 = *(const ulonglong2*)(sW + 2*(b*16 + 2*mp));
        FMA2(acc[2*mp], v, w2.x); FMA2(acc[2*mp+1], v, w2.y);
    }
}
__device__ __forceinline__ void fma_kb1(ull* acc, ull v, const float* sW, int b) {
    #pragma unroll
    for (int mp = 0; mp < 4; mp++) {
        ulonglong2 w2 = *(const ulonglong2*)(sW + 2*(b*16 + 2*mp));
        FMA2(acc[2*mp], v, w2.x); FMA2(acc[2*mp+1], v, w2.y);
    }
    ull w = *(const ull*)(sW + 2*(b*16 + 8));
    FMA2(acc[8], v, w);
}
__device__ __forceinline__ void fma_kb2(ull* acc, ull v, const float* sW, int b) {
    #pragma unroll
    for (int mp = 0; mp < 2; mp++) {
        ulonglong2 w2 = *(const ulonglong2*)(sW + 2*(b*16 + 2*mp));
        FMA2(acc[2*mp], v, w2.x); FMA2(acc[2*mp+1], v, w2.y);
    }
}

__global__ void __launch_bounds__(256) k_eqmp4(int N) {
    __shared__ float sWall[8][512];
    int t = threadIdx.x;
    int wid = t >> 5, lane = t & 31;
    int n = blockIdx.x * 8 + wid;
    float* sW = sWall[wid];

    int start = 0, cnt = 0;
    if (n < N) { start = g_starts[n]; cnt = g_counts[n]; }

    ull acc[30];
    #pragma unroll
    for (int i = 0; i < 30; i++) acc[i] = 0ull;

    int embc = (2*lane) & 31;
    float4 wa, wb;
    if (cnt > 0) {
        const float4* ws = (const float4*)(g_W + (size_t)start*256 + lane*8);
        wa = ws[0]; wb = ws[1];
    }

    for (int e = 0; e < cnt; e++) {
        __syncwarp();
        float4* d = (float4*)(sW + 16*lane);
        d[0] = make_float4(wa.x, wa.x, wa.y, wa.y);
        d[1] = make_float4(wa.z, wa.z, wa.w, wa.w);
        d[2] = make_float4(wb.x, wb.x, wb.y, wb.y);
        d[3] = make_float4(wb.z, wb.z, wb.w, wb.w);
        __syncwarp();
        int nbr = g_snbr[start + e];
        if (e + 1 < cnt) {
            const float4* ws = (const float4*)(g_W + (size_t)(start+e+1)*256 + lane*8);
            wa = ws[0]; wb = ws[1];
        }
        const float* EF = g_feats + (size_t)nbr * 1920 + 2*lane;
        ull emb2 = *(const ull*)(g_emb + nbr*32 + embc);

        ull ef[9];
        #pragma unroll
        for (int i = 0; i < 8; i++) ef[i] = *(const ull*)(EF + OFFS[i]);
        #pragma unroll
        for (int i = 0; i < 8; i++) {
            ull v; MUL2(v, ef[i], emb2);
            ef[i] = *(const ull*)(EF + OFFS[8+i]);
            fma_kb0(acc, v, sW, i);
        }
        #pragma unroll
        for (int i = 0; i < 8; i++) {
            ull v; MUL2(v, ef[i], emb2);
            ef[i] = *(const ull*)(EF + OFFS[i] + 64);
            fma_kb0(acc, v, sW, 8+i);
        }
        ef[8] = *(const ull*)(EF + OFFS[8] + 64);
        #pragma unroll
        for (int i = 0; i < 9; i++) {
            ull v; MUL2(v, ef[i], emb2);
            if (i < 4) ef[i] = *(const ull*)(EF + OFFS[i] + 128);
            if (i == 4) ef[4] = *(const ull*)(EF + 192);
            fma_kb1(acc + 16, v, sW, i);
        }
        #pragma unroll
        for (int i = 0; i < 4; i++) {
            ull v; MUL2(v, ef[i], emb2);
            fma_kb2(acc + 25, v, sW, i);
        }
        {
            ull v; MUL2(v, ef[4], emb2);
            ull w = *(const ull*)(sW);
            FMA2(acc[29], v, w);
        }
    }

    if (n < N) {
        float* orow = g_featsB + (size_t)n * 1920 + 2*lane;
        #pragma unroll
        for (int i = 0; i < 16; i++) {
            float lo, hi; UNPK2(lo, hi, acc[i]);
            *(float2*)(orow + OFFS[i]) = make_float2(0.1f*lo, 0.1f*hi);
        }
        #pragma unroll
        for (int i = 0; i < 9; i++) {
            float lo, hi; UNPK2(lo, hi, acc[16+i]);
            *(float2*)(orow + OFFS[i] + 64) = make_float2(0.1f*lo, 0.1f*hi);
        }
        #pragma unroll
        for (int i = 0; i < 4; i++) {
            float lo, hi; UNPK2(lo, hi, acc[25+i]);
            *(float2*)(orow + OFFS[i] + 128) = make_float2(0.1f*lo, 0.1f*hi);
        }
        {
            float lo, hi; UNPK2(lo, hi, acc[29]);
            *(float2*)(orow + 192) = make_float2(0.1f*lo, 0.1f*hi);
        }
    }
}

// ---------------- energy readout ----------------
__global__ void __launch_bounds__(256) k_energy(const float* __restrict__ wE,
                                                const float* __restrict__ bE,
                                                float* __restrict__ out, int N) {
    int n = blockIdx.x, t = threadIdx.x;
    float v = g_featsB[(size_t)n*1920 + t] * g_emb[n*32 + (t & 31)] * wE[t];
    #pragma unroll
    for (int o = 16; o > 0; o >>= 1) v += __shfl_xor_sync(0xffffffffu, v, o);
    __shared__ float sred[8];
    if ((t & 31) == 0) sred[t >> 5] = v;
    __syncthreads();
    if (t == 0) {
        float s = 0.f;
        #pragma unroll
        for (int w = 0; w < 8; w++) s += sred[w];
        out[n] = s + bE[0];
    }
}

// ---------------- host: numpy RandomState(0).randn ----------------
static void gen_cg(float* out) {
    static uint32_t mt[624];
    int mti;
    mt[0] = 0;
    for (int i = 1; i < 624; i++)
        mt[i] = 1812433253u * (mt[i-1] ^ (mt[i-1] >> 30)) + (uint32_t)i;
    mti = 624;
    auto genrand = [&]() -> uint32_t {
        if (mti >= 624) {
            for (int i = 0; i < 624; i++) {
                uint32_t y = (mt[i] & 0x80000000u) | (mt[(i+1) % 624] & 0x7fffffffu);
                mt[i] = mt[(i+397) % 624] ^ (y >> 1) ^ ((y & 1u) ? 2567483615u : 0u);
            }
            mti = 0;
        }
        uint32_t y = mt[mti++];
        y ^= y >> 11; y ^= (y << 7) & 2636928640u; y ^= (y << 15) & 4022730752u; y ^= y >> 18;
        return y;
    };
    auto rdouble = [&]() -> double {
        uint32_t a = genrand() >> 5, b = genrand() >> 6;
        return (a * 67108864.0 + b) / 9007199254740992.0;
    };
    bool has_g = false; double gcache = 0.0;
    auto gauss = [&]() -> double {
        if (has_g) { has_g = false; return gcache; }
        double x1, x2, r2;
        do {
            x1 = 2.0 * rdouble() - 1.0;
            x2 = 2.0 * rdouble() - 1.0;
            r2 = x1*x1 + x2*x2;
        } while (r2 >= 1.0 || r2 == 0.0);
        double f = sqrt(-2.0 * log(r2) / r2);
        gcache = f * x1; has_g = true;
        return f * x2;
    };
    for (int i = 0; i < 3436; i++) out[i] = (float)(gauss() * 0.2);
}

static CGBuf h_cg;

extern "C" void kernel_launch(void* const* d_in, const int* in_sizes, int n_in,
                              void* d_out, int out_size) {
    const float* sh      = (const float*)d_in[0];
    const float* rb      = (const float*)d_in[1];
    const float* tab     = (const float*)d_in[2];
    const float* wE      = (const float*)d_in[3];
    const float* bE      = (const float*)d_in[4];
    const int*   spec    = (const int*)d_in[5];
    const int*   centers = (const int*)d_in[6];
    const int*   nbrs    = (const int*)d_in[7];
    int N = in_sizes[5];
    int P = in_sizes[6];
    float* out = (float*)d_out;

    gen_cg(h_cg.v);

    k_initcg<<<1, 256>>>(h_cg);
    k_misc1<<<(N*240 + 255)/256, 256>>>(tab, spec, N);
    k_hist<<<(P + 255)/256, 256>>>(centers, P);
    k_scan<<<1, 1024>>>(N);
    k_scatter<<<(P + 255)/256, 256>>>(centers, P);
    k_edge<<<(16*P + 255)/256, 256>>>(sh, rb, nbrs, P);
    k_W2<<<(P + 63)/64, 256>>>(P);
    k_invA<<<(P*64 + 255)/256, 256>>>(sh, rb, centers, nbrs, spec, P);
    k_invB<<<(N*1920 + 255)/256, 256>>>(tab, N);
    k_tp0<<<(N + 3)/4, 256>>>(g_feats, N);
    k_tp1<<<(N + 3)/4, 256>>>(g_feats, N);
    k_tp23<<<(N + 1)/2, 256>>>(g_feats, N);
    k_eqmp4<<<(N + 7)/8, 256>>>(N);
    k_tp0<<<(N + 3)/4, 256>>>(g_featsB, N);
    k_tp1<<<(N + 3)/4, 256>>>(g_featsB, N);
    k_tp23<<<(N + 1)/2, 256>>>(g_featsB, N);
    k_energy<<<N, 256>>>(wE, bE, out, N);
}